// round 1
// baseline (speedup 1.0000x reference)
#include <cuda_runtime.h>

// ---------------- problem constants ----------------
#define N_EC   100000
#define N_DG   400000
#define N_CA3  120000
#define N_CA1  100000
#define T_STEPS 4
#define DT_     0.5f
#define A_IZH   0.02f
#define B_IZH   0.2f
#define TAU_I   0.9f
#define THR_I   1.0f
#define INH_GAIN 2.0f

// ---------------- persistent device state ----------------
__device__ float g_ec_v[N_EC],  g_ec_u[N_EC],  g_ec_s[N_EC];
__device__ float g_dg_v[N_DG],  g_dg_u[N_DG],  g_dg_s[N_DG],  g_dg_I[N_DG];
__device__ float g_c3_v[N_CA3], g_c3_u[N_CA3], g_c3_s[N_CA3], g_c3_I[N_CA3];
__device__ float g_c1_v[N_CA1], g_c1_u[N_CA1],               g_c1_I[N_CA1];

// double-buffered scalars, indexed [pop*2 + (t&1)]
__device__ float g_sum[6];  // synaptic-input sums: 0/1=dg, 2/3=c3, 4/5=c1
__device__ int   g_cnt[6];  // spike counts:        0/1=ec, 2/3=dg, 4/5=c3
__device__ float g_iv[6];   // inhibitory LIF v:    0/1=dg, 2/3=c3, 4/5=c1

// ---------------- init ----------------
__global__ void init_kernel() {
    int i = blockIdx.x * blockDim.x + threadIdx.x;
    if (i < N_EC)  { g_ec_v[i] = -65.f; g_ec_u[i] = B_IZH * -65.f; g_ec_s[i] = 0.f; }
    if (i < N_DG)  { g_dg_v[i] = -65.f; g_dg_u[i] = B_IZH * -65.f; g_dg_s[i] = 0.f; g_dg_I[i] = 0.f; }
    if (i < N_CA3) { g_c3_v[i] = -65.f; g_c3_u[i] = B_IZH * -65.f; g_c3_s[i] = 0.f; g_c3_I[i] = 0.f; }
    if (i < N_CA1) { g_c1_v[i] = -65.f; g_c1_u[i] = B_IZH * -65.f;                  g_c1_I[i] = 0.f; }
    if (i < 6)     { g_sum[i] = 0.f; g_cnt[i] = 0; g_iv[i] = 0.f; }
}

// ---------------- izhikevich step (with fused scalar-LIF inhibition) ----------------
__global__ void izh_kernel(int n,
                           float* __restrict__ v, float* __restrict__ u,
                           const float* __restrict__ c, const float* __restrict__ d,
                           const float* __restrict__ drive,   // external current or null
                           float* __restrict__ Iarr,          // synaptic current (read+zero) or null
                           const float* __restrict__ sum_rd,  // input-sum slot or null (no inhibition)
                           float* __restrict__ sum_zero,      // other sum slot to zero
                           float nrm,                         // 1/n_target for the mean
                           const float* __restrict__ iv_rd, float* __restrict__ iv_wr,
                           float* __restrict__ s_out,         // spike output or null
                           int* __restrict__ cnt_wr, int* __restrict__ cnt_zero)
{
    int i = blockIdx.x * blockDim.x + threadIdx.x;

    float inh = 0.f;
    if (sum_rd) {
        // scalar LIF: every inhibitory neuron gets the identical mean input from
        // identical state, so the population is a single scalar. All threads
        // recompute it read-only; thread 0 commits the next-step state.
        float mean = (*sum_rd) * nrm;
        float ivn  = TAU_I * (*iv_rd) + (1.f - TAU_I) * mean;
        float sp   = (ivn >= THR_I) ? 1.f : 0.f;
        inh = INH_GAIN * sp;
        if (i == 0) {
            *iv_wr   = (sp > 0.f) ? 0.f : ivn;
            *sum_zero = 0.f;
        }
    }
    if (i == 0 && cnt_zero) *cnt_zero = 0;
    if (i >= n) return;

    float I = inh == 0.f ? 0.f : -inh;
    if (drive) I += drive[i];
    if (Iarr)  { I += Iarr[i]; Iarr[i] = 0.f; }   // consume & clear for next step

    float vv = v[i], uu = u[i];
    vv = vv + (0.04f * vv * vv + 5.f * vv + 140.f - uu + I) * DT_;
    vv = fminf(fmaxf(vv, -90.f), 40.f);
    uu = uu + A_IZH * (B_IZH * vv - uu) * DT_;     // uses post-clamp v (matches ref)
    bool sp = (vv >= 30.f);
    if (s_out) s_out[i] = sp ? 1.f : 0.f;
    if (sp) { vv = c[i]; uu += d[i]; }
    v[i] = vv; u[i] = uu;

    if (cnt_wr && sp) atomicAdd(cnt_wr, 1);
}

// ---------------- sparse transmit: I[tgt] += val * spk[src], plus sum for the mean ----------------
__global__ void transmit_kernel(int nnz,
                                const int*   __restrict__ src,
                                const int*   __restrict__ tgt,
                                const float* __restrict__ val,
                                const float* __restrict__ spk,
                                float* __restrict__ Iarr,
                                const int*   __restrict__ cnt,   // source spike count
                                float* __restrict__ sum_wr)
{
    // Data-dependent early exit: if no source neuron spiked, every contribution
    // is exactly zero and Iarr/sum are already zeroed — skip the edge stream.
    if (*cnt == 0) return;

    float local = 0.f;
    int stride = gridDim.x * blockDim.x;
    for (int e = blockIdx.x * blockDim.x + threadIdx.x; e < nnz; e += stride) {
        float s = spk[src[e]];
        if (s != 0.f) {
            float w = val[e] * s;
            atomicAdd(&Iarr[tgt[e]], w);
            local += w;
        }
    }
    // block-reduce local sums -> single atomic per block
    #pragma unroll
    for (int o = 16; o; o >>= 1) local += __shfl_down_sync(0xffffffffu, local, o);
    __shared__ float sh[32];
    if ((threadIdx.x & 31) == 0) sh[threadIdx.x >> 5] = local;
    __syncthreads();
    if (threadIdx.x < 32) {
        float x = (threadIdx.x < (blockDim.x >> 5)) ? sh[threadIdx.x] : 0.f;
        #pragma unroll
        for (int o = 16; o; o >>= 1) x += __shfl_down_sync(0xffffffffu, x, o);
        if (threadIdx.x == 0 && x != 0.f) atomicAdd(sum_wr, x);
    }
}

__global__ void copy_out_kernel(float* __restrict__ out) {
    int i = blockIdx.x * blockDim.x + threadIdx.x;
    if (i < N_CA1) out[i] = g_c1_v[i];
}

// ---------------- launch ----------------
static inline int cdiv(int a, int b) { return (a + b - 1) / b; }

extern "C" void kernel_launch(void* const* d_in, const int* in_sizes, int n_in,
                              void* d_out, int out_size)
{
    const float* drive  = (const float*)d_in[0];
    const int*   pp_src = (const int*)  d_in[1];
    const int*   pp_tgt = (const int*)  d_in[2];
    const float* pp_val = (const float*)d_in[3];
    const int*   mf_src = (const int*)  d_in[4];
    const int*   mf_tgt = (const int*)  d_in[5];
    const float* mf_val = (const float*)d_in[6];
    const int*   rc_src = (const int*)  d_in[7];
    const int*   rc_tgt = (const int*)  d_in[8];
    const float* rc_val = (const float*)d_in[9];
    const int*   sc_src = (const int*)  d_in[10];
    const int*   sc_tgt = (const int*)  d_in[11];
    const float* sc_val = (const float*)d_in[12];
    const float* ec_c  = (const float*)d_in[13];
    const float* ec_d  = (const float*)d_in[14];
    const float* dg_c  = (const float*)d_in[15];
    const float* dg_d  = (const float*)d_in[16];
    const float* ca3_c = (const float*)d_in[17];
    const float* ca3_d = (const float*)d_in[18];
    const float* ca1_c = (const float*)d_in[19];
    const float* ca1_d = (const float*)d_in[20];

    const int pp_nnz = in_sizes[1];
    const int mf_nnz = in_sizes[4];
    const int rc_nnz = in_sizes[7];
    const int sc_nnz = in_sizes[10];

    // resolve device-global addresses (capture-time only; free on replay)
    float *ec_v, *ec_u, *ec_s, *dg_v, *dg_u, *dg_s, *dg_I;
    float *c3_v, *c3_u, *c3_s, *c3_I, *c1_v, *c1_u, *c1_I;
    float *sum, *iv; int* cnt;
    cudaGetSymbolAddress((void**)&ec_v, g_ec_v);  cudaGetSymbolAddress((void**)&ec_u, g_ec_u);
    cudaGetSymbolAddress((void**)&ec_s, g_ec_s);
    cudaGetSymbolAddress((void**)&dg_v, g_dg_v);  cudaGetSymbolAddress((void**)&dg_u, g_dg_u);
    cudaGetSymbolAddress((void**)&dg_s, g_dg_s);  cudaGetSymbolAddress((void**)&dg_I, g_dg_I);
    cudaGetSymbolAddress((void**)&c3_v, g_c3_v);  cudaGetSymbolAddress((void**)&c3_u, g_c3_u);
    cudaGetSymbolAddress((void**)&c3_s, g_c3_s);  cudaGetSymbolAddress((void**)&c3_I, g_c3_I);
    cudaGetSymbolAddress((void**)&c1_v, g_c1_v);  cudaGetSymbolAddress((void**)&c1_u, g_c1_u);
    cudaGetSymbolAddress((void**)&c1_I, g_c1_I);
    cudaGetSymbolAddress((void**)&sum, g_sum);
    cudaGetSymbolAddress((void**)&cnt, g_cnt);
    cudaGetSymbolAddress((void**)&iv,  g_iv);

    const int TPB = 256;
    const int TGRID = 2048;   // grid-stride edge kernels

    init_kernel<<<cdiv(N_DG, TPB), TPB>>>();

    for (int t = 0; t < T_STEPS; ++t) {
        int a = t & 1, b = (t + 1) & 1;

        // --- EC: external drive only, no inhibition ---
        izh_kernel<<<cdiv(N_EC, TPB), TPB>>>(
            N_EC, ec_v, ec_u, ec_c, ec_d,
            drive + (size_t)t * N_EC, nullptr,
            nullptr, nullptr, 0.f, nullptr, nullptr,
            ec_s, &cnt[0 + a], &cnt[0 + b]);

        // --- perforant path EC->DG ---
        transmit_kernel<<<TGRID, TPB>>>(pp_nnz, pp_src, pp_tgt, pp_val, ec_s,
                                        dg_I, &cnt[0 + a], &sum[0 + a]);

        // --- DG (with scalar-LIF inhibition) ---
        izh_kernel<<<cdiv(N_DG, TPB), TPB>>>(
            N_DG, dg_v, dg_u, dg_c, dg_d,
            nullptr, dg_I,
            &sum[0 + a], &sum[0 + b], 1.f / N_DG, &iv[0 + a], &iv[0 + b],
            dg_s, &cnt[2 + a], &cnt[2 + b]);

        // --- mossy fibers DG->CA3, and CA3 recurrent (previous-step spikes) ---
        transmit_kernel<<<TGRID, TPB>>>(mf_nnz, mf_src, mf_tgt, mf_val, dg_s,
                                        c3_I, &cnt[2 + a], &sum[2 + a]);
        transmit_kernel<<<TGRID, TPB>>>(rc_nnz, rc_src, rc_tgt, rc_val, c3_s,
                                        c3_I, &cnt[4 + b], &sum[2 + a]); // prev-step cnt slot

        // --- CA3 ---
        izh_kernel<<<cdiv(N_CA3, TPB), TPB>>>(
            N_CA3, c3_v, c3_u, ca3_c, ca3_d,
            nullptr, c3_I,
            &sum[2 + a], &sum[2 + b], 1.f / N_CA3, &iv[2 + a], &iv[2 + b],
            c3_s, &cnt[4 + a], &cnt[4 + b]);

        // --- Schaffer collaterals CA3->CA1 ---
        transmit_kernel<<<TGRID, TPB>>>(sc_nnz, sc_src, sc_tgt, sc_val, c3_s,
                                        c1_I, &cnt[4 + a], &sum[4 + a]);

        // --- CA1 (no spike output needed downstream) ---
        izh_kernel<<<cdiv(N_CA1, TPB), TPB>>>(
            N_CA1, c1_v, c1_u, ca1_c, ca1_d,
            nullptr, c1_I,
            &sum[4 + a], &sum[4 + b], 1.f / N_CA1, &iv[4 + a], &iv[4 + b],
            nullptr, nullptr, nullptr);
    }

    copy_out_kernel<<<cdiv(N_CA1, TPB), TPB>>>((float*)d_out);
}

// round 2
// speedup vs baseline: 7.0933x; 7.0933x over previous
#include <cuda_runtime.h>

// ---------------- problem constants ----------------
#define N_EC   100000
#define N_DG   400000
#define N_CA3  120000
#define N_CA1  100000
#define T_STEPS 4
#define DT_     0.5f
#define A_IZH   0.02f
#define B_IZH   0.2f
#define TAU_I   0.9f
#define THR_I   1.0f
#define INH_GAIN 2.0f

#define TPB      256
#define MIN_BPSM 4      // guaranteed-resident blocks per SM (launch_bounds enforces)

// ---------------- persistent device state (fallback only) ----------------
__device__ float g_ec_v[N_EC],  g_ec_u[N_EC],  g_ec_s[N_EC];
__device__ float g_dg_v[N_DG],  g_dg_u[N_DG],  g_dg_s[N_DG],  g_dg_I[N_DG];
__device__ float g_c3_v[N_CA3], g_c3_u[N_CA3], g_c3_s[N_CA3], g_c3_I[N_CA3];
__device__ float g_c1_v[N_CA1], g_c1_u[N_CA1],                g_c1_I[N_CA1];
__device__ float g_sum[6], g_iv[6];     // double-buffered scalars [pop*2 + (t&1)]
__device__ int   g_flag = 0;            // any-spike flag (pre-zeroed invariant)

// grid barrier state (invariant: count==0 at kernel entry/exit)
__device__ unsigned          g_bar_count = 0;
__device__ volatile unsigned g_bar_sense = 0;

// ---------------- grid-wide barrier (sense-reversing, self-resetting) ----------------
__device__ __forceinline__ void gsync(unsigned nb, unsigned& ls) {
    __syncthreads();
    if (threadIdx.x == 0) {
        unsigned s = ls ^ 1u; ls = s;
        __threadfence();
        if (atomicAdd(&g_bar_count, 1u) == nb - 1u) {
            g_bar_count = 0u;          // reset for next barrier / next launch
            __threadfence();
            g_bar_sense = s;           // release
        } else {
            while (g_bar_sense != s) __nanosleep(64);
        }
        __threadfence();
    }
    __syncthreads();
}

// ---------------- Izhikevich single step (matches reference op order) ----------------
__device__ __forceinline__ bool izh_step(float& v, float& u, float I,
                                         const float* __restrict__ c,
                                         const float* __restrict__ d, int i) {
    v += (0.04f * v * v + 5.f * v + 140.f - u + I) * DT_;
    v = fminf(fmaxf(v, -90.f), 40.f);
    u += A_IZH * (B_IZH * v - u) * DT_;     // uses post-clamp v (matches ref)
    bool sp = (v >= 30.f);
    if (sp) { v = c[i]; u += d[i]; }
    return sp;
}

// ---------------- fallback helpers ----------------
__device__ void fb_transmit(int nnz, const int* __restrict__ src,
                            const int* __restrict__ tgt, const float* __restrict__ val,
                            const float* __restrict__ spk, float* __restrict__ Iarr,
                            float* sum_wr, int gt, int gs)
{
    float local = 0.f;
    for (int e = gt; e < nnz; e += gs) {
        float s = __ldcg(&spk[src[e]]);           // bypass L1: written by other threads
        if (s != 0.f) {
            float w = val[e] * s;
            atomicAdd(&Iarr[tgt[e]], w);
            local += w;
        }
    }
    #pragma unroll
    for (int o = 16; o; o >>= 1) local += __shfl_down_sync(0xffffffffu, local, o);
    if ((threadIdx.x & 31) == 0 && local != 0.f) atomicAdd(sum_wr, local);
}

__device__ void fb_izh_pop(int n, float* v, float* u,
                           const float* c, const float* d,
                           float* Iarr, float* s,
                           const float* sum_rd, float* sum_zero, float nrm,
                           const float* iv_rd, float* iv_wr,
                           float* outv, int gt, int gs)
{
    // scalar inhibitory LIF: whole population is one scalar (identical input/state)
    float mean = (*(volatile const float*)sum_rd) * nrm;
    float ivn  = TAU_I * (*(volatile const float*)iv_rd) + (1.f - TAU_I) * mean;
    float spI  = (ivn >= THR_I) ? 1.f : 0.f;
    float inh  = INH_GAIN * spI;
    if (gt == 0) { *iv_wr = (spI > 0.f) ? 0.f : ivn; *sum_zero = 0.f; }

    for (int i = gt; i < n; i += gs) {
        float I = __ldcg(&Iarr[i]) - inh;         // bypass L1: atomics landed in L2
        Iarr[i] = 0.f;                            // consume & clear
        float vv = v[i], uu = u[i];
        bool sp = izh_step(vv, uu, I, c, d, i);
        if (s) s[i] = sp ? 1.f : 0.f;
        v[i] = vv; u[i] = uu;
        if (outv) outv[i] = vv;
    }
}

// ---------------- the one kernel ----------------
__global__ __launch_bounds__(TPB, MIN_BPSM)
void hippo_kernel(const float* __restrict__ drive,
                  const int* pp_src, const int* pp_tgt, const float* pp_val, int pp_nnz,
                  const int* mf_src, const int* mf_tgt, const float* mf_val, int mf_nnz,
                  const int* rc_src, const int* rc_tgt, const float* rc_val, int rc_nnz,
                  const int* sc_src, const int* sc_tgt, const float* sc_val, int sc_nnz,
                  const float* ec_c, const float* ec_d, const float* dg_c, const float* dg_d,
                  const float* ca3_c, const float* ca3_d, const float* ca1_c, const float* ca1_d,
                  float* __restrict__ out, unsigned nb)
{
    const int gt = blockIdx.x * TPB + threadIdx.x;
    const int gs = (int)nb * TPB;
    unsigned ls = g_bar_sense;     // barrier sense snapshot (no barrier active at entry)

    // ================= optimistic fast path (zero spikes everywhere) =================
    bool any = false;

    // EC: drive-dependent per-neuron rollout, state held in registers across all steps
    for (int i = gt; i < N_EC; i += gs) {
        float v = -65.f, u = B_IZH * -65.f;
        #pragma unroll
        for (int t = 0; t < T_STEPS; t++)
            any |= izh_step(v, u, drive[t * N_EC + i], ec_c, ec_d, i);
    }

    // DG / CA3 / CA1 under zero input + zero inhibition are population-uniform:
    // one scalar trajectory each (spike -> per-neuron divergence -> flag -> fallback).
    {
        float v = -65.f, u = B_IZH * -65.f;
        #pragma unroll
        for (int t = 0; t < T_STEPS; t++) any |= izh_step(v, u, 0.f, dg_c, dg_d, 0);
    }
    {
        float v = -65.f, u = B_IZH * -65.f;
        #pragma unroll
        for (int t = 0; t < T_STEPS; t++) any |= izh_step(v, u, 0.f, ca3_c, ca3_d, 0);
    }
    float c1v;
    {
        float v = -65.f, u = B_IZH * -65.f;
        #pragma unroll
        for (int t = 0; t < T_STEPS; t++) any |= izh_step(v, u, 0.f, ca1_c, ca1_d, 0);
        c1v = v;
    }
    // write output optimistically (fallback overwrites if invalid)
    for (int i = gt; i < N_CA1; i += gs) out[i] = c1v;

    if (any) *(volatile int*)&g_flag = 1;

    gsync(nb, ls);                                      // the ONLY barrier on the fast path

    if (*(volatile int*)&g_flag == 0) return;           // validated: done

    // ================= exact fallback: full step-wise simulation =================
    // init all state
    for (int i = gt; i < N_DG; i += gs) {
        if (i < N_EC)  { g_ec_v[i] = -65.f; g_ec_u[i] = B_IZH * -65.f; g_ec_s[i] = 0.f; }
        g_dg_v[i] = -65.f; g_dg_u[i] = B_IZH * -65.f; g_dg_s[i] = 0.f; g_dg_I[i] = 0.f;
        if (i < N_CA3) { g_c3_v[i] = -65.f; g_c3_u[i] = B_IZH * -65.f; g_c3_s[i] = 0.f; g_c3_I[i] = 0.f; }
        if (i < N_CA1) { g_c1_v[i] = -65.f; g_c1_u[i] = B_IZH * -65.f; g_c1_I[i] = 0.f; }
    }
    if (gt == 0) {
        #pragma unroll
        for (int k = 0; k < 6; k++) { g_sum[k] = 0.f; g_iv[k] = 0.f; }
        g_flag = 0;                                     // restore pre-zeroed invariant
    }
    gsync(nb, ls);

    for (int t = 0; t < T_STEPS; t++) {
        int a = t & 1, b = a ^ 1;

        // EC izh (external drive only, no inhibition)
        for (int i = gt; i < N_EC; i += gs) {
            float v = g_ec_v[i], u = g_ec_u[i];
            bool sp = izh_step(v, u, drive[t * N_EC + i], ec_c, ec_d, i);
            g_ec_s[i] = sp ? 1.f : 0.f; g_ec_v[i] = v; g_ec_u[i] = u;
        }
        gsync(nb, ls);

        // perforant path EC->DG
        fb_transmit(pp_nnz, pp_src, pp_tgt, pp_val, g_ec_s, g_dg_I, &g_sum[0 + a], gt, gs);
        gsync(nb, ls);

        // DG
        fb_izh_pop(N_DG, g_dg_v, g_dg_u, dg_c, dg_d, g_dg_I, g_dg_s,
                   &g_sum[0 + a], &g_sum[0 + b], 1.f / N_DG, &g_iv[0 + a], &g_iv[0 + b],
                   nullptr, gt, gs);
        gsync(nb, ls);

        // mossy fibers DG->CA3 + CA3 recurrent (prev-step spikes) — one phase
        fb_transmit(mf_nnz, mf_src, mf_tgt, mf_val, g_dg_s, g_c3_I, &g_sum[2 + a], gt, gs);
        fb_transmit(rc_nnz, rc_src, rc_tgt, rc_val, g_c3_s, g_c3_I, &g_sum[2 + a], gt, gs);
        gsync(nb, ls);

        // CA3
        fb_izh_pop(N_CA3, g_c3_v, g_c3_u, ca3_c, ca3_d, g_c3_I, g_c3_s,
                   &g_sum[2 + a], &g_sum[2 + b], 1.f / N_CA3, &g_iv[2 + a], &g_iv[2 + b],
                   nullptr, gt, gs);
        gsync(nb, ls);

        // Schaffer collaterals CA3->CA1
        fb_transmit(sc_nnz, sc_src, sc_tgt, sc_val, g_c3_s, g_c1_I, &g_sum[4 + a], gt, gs);
        gsync(nb, ls);

        // CA1 (no downstream consumers; barrier after it not needed — next phases
        // touching its scalars/arrays are >=3 barriers away)
        fb_izh_pop(N_CA1, g_c1_v, g_c1_u, ca1_c, ca1_d, g_c1_I, nullptr,
                   &g_sum[4 + a], &g_sum[4 + b], 1.f / N_CA1, &g_iv[4 + a], &g_iv[4 + b],
                   (t == T_STEPS - 1) ? out : nullptr, gt, gs);
        if (t < T_STEPS - 1) gsync(nb, ls);
    }
}

// ---------------- launch ----------------
extern "C" void kernel_launch(void* const* d_in, const int* in_sizes, int n_in,
                              void* d_out, int out_size)
{
    const float* drive  = (const float*)d_in[0];
    const int*   pp_src = (const int*)  d_in[1];
    const int*   pp_tgt = (const int*)  d_in[2];
    const float* pp_val = (const float*)d_in[3];
    const int*   mf_src = (const int*)  d_in[4];
    const int*   mf_tgt = (const int*)  d_in[5];
    const float* mf_val = (const float*)d_in[6];
    const int*   rc_src = (const int*)  d_in[7];
    const int*   rc_tgt = (const int*)  d_in[8];
    const float* rc_val = (const float*)d_in[9];
    const int*   sc_src = (const int*)  d_in[10];
    const int*   sc_tgt = (const int*)  d_in[11];
    const float* sc_val = (const float*)d_in[12];
    const float* ec_c  = (const float*)d_in[13];
    const float* ec_d  = (const float*)d_in[14];
    const float* dg_c  = (const float*)d_in[15];
    const float* dg_d  = (const float*)d_in[16];
    const float* ca3_c = (const float*)d_in[17];
    const float* ca3_d = (const float*)d_in[18];
    const float* ca1_c = (const float*)d_in[19];
    const float* ca1_d = (const float*)d_in[20];

    const int pp_nnz = in_sizes[1];
    const int mf_nnz = in_sizes[4];
    const int rc_nnz = in_sizes[7];
    const int sc_nnz = in_sizes[10];

    int dev = 0;  cudaGetDevice(&dev);
    int sms = 0;  cudaDeviceGetAttribute(&sms, cudaDevAttrMultiProcessorCount, dev);
    unsigned nb = (unsigned)(sms * MIN_BPSM);   // residency guaranteed by __launch_bounds__

    hippo_kernel<<<nb, TPB>>>(drive,
                              pp_src, pp_tgt, pp_val, pp_nnz,
                              mf_src, mf_tgt, mf_val, mf_nnz,
                              rc_src, rc_tgt, rc_val, rc_nnz,
                              sc_src, sc_tgt, sc_val, sc_nnz,
                              ec_c, ec_d, dg_c, dg_d, ca3_c, ca3_d, ca1_c, ca1_d,
                              (float*)d_out, nb);
}

// round 8
// speedup vs baseline: 11.7536x; 1.6570x over previous
#include <cuda_runtime.h>

// ---------------- problem constants ----------------
#define N_EC   100000
#define N_DG   400000
#define N_CA3  120000
#define N_CA1  100000
#define T_STEPS 4
#define DT_     0.5f
#define A_IZH   0.02f
#define B_IZH   0.2f
#define TAU_I   0.9f
#define THR_I   1.0f
#define INH_GAIN 2.0f

#define TPB 256

// ---------------- persistent device state ----------------
// fallback-only per-neuron state
__device__ float g_ec_v[N_EC],  g_ec_u[N_EC],  g_ec_s[N_EC];
__device__ float g_dg_v[N_DG],  g_dg_u[N_DG],  g_dg_s[N_DG],  g_dg_I[N_DG];
__device__ float g_c3_v[N_CA3], g_c3_u[N_CA3], g_c3_s[N_CA3], g_c3_I[N_CA3];
__device__ float g_c1_v[N_CA1], g_c1_u[N_CA1],                g_c1_I[N_CA1];

__device__ int      g_flag = 0;        // any-spike flag  (invariant: 0 at entry/exit)
__device__ unsigned g_arrive = 0;      // arrival counter (invariant: 0 at entry/exit)

// ---------------- fast-path izh step: spike DETECTION only ----------------
// After a spike the trajectory no longer needs to be exact (the flag forces the
// exact fallback), so no c/d loads and no reset here.
__device__ __forceinline__ void istep(float& v, float& u, float I, bool& any) {
    v += (0.04f * v * v + 5.f * v + 140.f - u + I) * DT_;
    v = fminf(fmaxf(v, -90.f), 40.f);
    u += A_IZH * (B_IZH * v - u) * DT_;
    any |= (v >= 30.f);
}

// ---------------- exact fallback helpers (single block; cold path) ----------------
__device__ void fb_trans(int nnz, const int* __restrict__ src, const int* __restrict__ tgt,
                         const float* __restrict__ val, const float* __restrict__ spk,
                         float* __restrict__ Iarr, float* sum)
{
    float local = 0.f;
    for (int e = threadIdx.x; e < nnz; e += TPB) {
        float s = spk[src[e]];
        if (s != 0.f) { float w = val[e] * s; atomicAdd(&Iarr[tgt[e]], w); local += w; }
    }
    #pragma unroll
    for (int o = 16; o; o >>= 1) local += __shfl_down_sync(0xffffffffu, local, o);
    if ((threadIdx.x & 31) == 0 && local != 0.f) atomicAdd(sum, local);
}

__device__ void fb_pop(int nc, float* v, float* u, const float* c, const float* d,
                       float* Iarr, float* s, float* sum, float* iv, float nrm, float* outv)
{
    // scalar inhibitory LIF (whole inhibitory population is one scalar:
    // identical input jnp.full(mean) from identical zero init)
    float mean = *sum * nrm;
    float ivn  = TAU_I * (*iv) + (1.f - TAU_I) * mean;
    float spI  = (ivn >= THR_I) ? 1.f : 0.f;
    float inh  = INH_GAIN * spI;
    __syncthreads();
    if (threadIdx.x == 0) { *iv = (spI > 0.f) ? 0.f : ivn; *sum = 0.f; }
    for (int i = threadIdx.x; i < nc; i += TPB) {
        float I = Iarr[i] - inh;  Iarr[i] = 0.f;
        float vv = v[i], uu = u[i];
        vv += (0.04f * vv * vv + 5.f * vv + 140.f - uu + I) * DT_;
        vv = fminf(fmaxf(vv, -90.f), 40.f);
        uu += A_IZH * (B_IZH * vv - uu) * DT_;   // post-clamp v, matches reference
        bool sp = (vv >= 30.f);
        if (s) s[i] = sp ? 1.f : 0.f;
        if (sp) { vv = c[i]; uu += d[i]; }
        v[i] = vv; u[i] = uu;
        if (outv) outv[i] = vv;
    }
    __syncthreads();
}

// ---------------- the one kernel ----------------
__global__ __launch_bounds__(TPB)
void hippo_kernel(const float* __restrict__ drive,
                  const int* pp_src, const int* pp_tgt, const float* pp_val, int pp_nnz,
                  const int* mf_src, const int* mf_tgt, const float* mf_val, int mf_nnz,
                  const int* rc_src, const int* rc_tgt, const float* rc_val, int rc_nnz,
                  const int* sc_src, const int* sc_tgt, const float* sc_val, int sc_nnz,
                  const float* ec_c, const float* ec_d, const float* dg_c, const float* dg_d,
                  const float* ca3_c, const float* ca3_d, const float* ca1_c, const float* ca1_d,
                  float* __restrict__ out, unsigned nb)
{
    const int tid = threadIdx.x;
    const int gt  = blockIdx.x * TPB + tid;
    const int gs  = (int)nb * TPB;

    // ===== fast path: exact zero-spike rollout =====
    bool any = false;

    // DG/CA3/CA1 under zero input + identical init are population-uniform:
    // one scalar trajectory each. No runtime data involved -> the compiler
    // constant-folds these rollouts (c1v and their spike flags are literals).
    {
        float v = -65.f, u = B_IZH * -65.f;
        #pragma unroll
        for (int t = 0; t < T_STEPS; t++) istep(v, u, 0.f, any);
    }
    {
        float v = -65.f, u = B_IZH * -65.f;
        #pragma unroll
        for (int t = 0; t < T_STEPS; t++) istep(v, u, 0.f, any);
    }
    float c1v;
    {
        float v = -65.f, u = B_IZH * -65.f;
        #pragma unroll
        for (int t = 0; t < T_STEPS; t++) istep(v, u, 0.f, any);
        c1v = v;
    }

    // EC: drive-dependent, float4-vectorized, all 4 timestep loads issued up front
    const float4* dr4 = (const float4*)drive;
    const int NG = N_EC / 4;
    for (int g = gt; g < NG; g += gs) {
        float4 D0 = dr4[0 * NG + g];
        float4 D1 = dr4[1 * NG + g];
        float4 D2 = dr4[2 * NG + g];
        float4 D3 = dr4[3 * NG + g];
        #define EC_LANE(comp) { \
            float v = -65.f, u = B_IZH * -65.f; \
            istep(v, u, D0.comp, any); istep(v, u, D1.comp, any); \
            istep(v, u, D2.comp, any); istep(v, u, D3.comp, any); }
        EC_LANE(x) EC_LANE(y) EC_LANE(z) EC_LANE(w)
        #undef EC_LANE
    }

    // optimistic output (the fallback overwrites it if any spike occurred)
    float4* out4 = (float4*)out;
    const float4 o4 = make_float4(c1v, c1v, c1v, c1v);
    for (int g = gt; g < N_CA1 / 4; g += gs) out4[g] = o4;

    if (any) g_flag = 1;

    // ===== arrive-only "barrier": non-last blocks exit without waiting =====
    __threadfence();                       // order out/flag stores before arrive
    __syncthreads();
    __shared__ unsigned s_ticket;
    if (tid == 0) s_ticket = atomicAdd(&g_arrive, 1u);
    __syncthreads();
    if (s_ticket != nb - 1u) return;       // fast exit: no spinning anywhere

    // ----- last-arriving block: validate -----
    if (tid == 0) g_arrive = 0;            // restore invariant for next replay
    __threadfence();                       // acquire side of the arrive chain
    if (*(volatile int*)&g_flag == 0) return;

    // ===== exact fallback (spikes detected): full sim in this one block =====
    if (tid == 0) g_flag = 0;
    for (int i = tid; i < N_DG; i += TPB) {
        if (i < N_EC)  { g_ec_v[i] = -65.f; g_ec_u[i] = B_IZH * -65.f; g_ec_s[i] = 0.f; }
        g_dg_v[i] = -65.f; g_dg_u[i] = B_IZH * -65.f; g_dg_s[i] = 0.f; g_dg_I[i] = 0.f;
        if (i < N_CA3) { g_c3_v[i] = -65.f; g_c3_u[i] = B_IZH * -65.f; g_c3_s[i] = 0.f; g_c3_I[i] = 0.f; }
        if (i < N_CA1) { g_c1_v[i] = -65.f; g_c1_u[i] = B_IZH * -65.f; g_c1_I[i] = 0.f; }
    }
    __shared__ float s_sum[3], s_iv[3];
    if (tid < 3) { s_sum[tid] = 0.f; s_iv[tid] = 0.f; }
    __syncthreads();

    for (int t = 0; t < T_STEPS; t++) {
        // EC (drive only, no inhibition)
        for (int i = tid; i < N_EC; i += TPB) {
            float v = g_ec_v[i], u = g_ec_u[i];
            v += (0.04f * v * v + 5.f * v + 140.f - u + drive[t * N_EC + i]) * DT_;
            v = fminf(fmaxf(v, -90.f), 40.f);
            u += A_IZH * (B_IZH * v - u) * DT_;
            bool sp = (v >= 30.f);
            g_ec_s[i] = sp ? 1.f : 0.f;
            if (sp) { v = ec_c[i]; u += ec_d[i]; }
            g_ec_v[i] = v; g_ec_u[i] = u;
        }
        __syncthreads();

        fb_trans(pp_nnz, pp_src, pp_tgt, pp_val, g_ec_s, g_dg_I, &s_sum[0]);
        __syncthreads();
        fb_pop(N_DG, g_dg_v, g_dg_u, dg_c, dg_d, g_dg_I, g_dg_s,
               &s_sum[0], &s_iv[0], 1.f / N_DG, nullptr);

        fb_trans(mf_nnz, mf_src, mf_tgt, mf_val, g_dg_s, g_c3_I, &s_sum[1]);
        fb_trans(rc_nnz, rc_src, rc_tgt, rc_val, g_c3_s, g_c3_I, &s_sum[1]);
        __syncthreads();
        fb_pop(N_CA3, g_c3_v, g_c3_u, ca3_c, ca3_d, g_c3_I, g_c3_s,
               &s_sum[1], &s_iv[1], 1.f / N_CA3, nullptr);

        fb_trans(sc_nnz, sc_src, sc_tgt, sc_val, g_c3_s, g_c1_I, &s_sum[2]);
        __syncthreads();
        fb_pop(N_CA1, g_c1_v, g_c1_u, ca1_c, ca1_d, g_c1_I, nullptr,
               &s_sum[2], &s_iv[2], 1.f / N_CA1,
               (t == T_STEPS - 1) ? out : nullptr);
    }
}

// ---------------- launch ----------------
extern "C" void kernel_launch(void* const* d_in, const int* in_sizes, int n_in,
                              void* d_out, int out_size)
{
    const float* drive  = (const float*)d_in[0];
    const int*   pp_src = (const int*)  d_in[1];
    const int*   pp_tgt = (const int*)  d_in[2];
    const float* pp_val = (const float*)d_in[3];
    const int*   mf_src = (const int*)  d_in[4];
    const int*   mf_tgt = (const int*)  d_in[5];
    const float* mf_val = (const float*)d_in[6];
    const int*   rc_src = (const int*)  d_in[7];
    const int*   rc_tgt = (const int*)  d_in[8];
    const float* rc_val = (const float*)d_in[9];
    const int*   sc_src = (const int*)  d_in[10];
    const int*   sc_tgt = (const int*)  d_in[11];
    const float* sc_val = (const float*)d_in[12];
    const float* ec_c  = (const float*)d_in[13];
    const float* ec_d  = (const float*)d_in[14];
    const float* dg_c  = (const float*)d_in[15];
    const float* dg_d  = (const float*)d_in[16];
    const float* ca3_c = (const float*)d_in[17];
    const float* ca3_d = (const float*)d_in[18];
    const float* ca1_c = (const float*)d_in[19];
    const float* ca1_d = (const float*)d_in[20];

    const int pp_nnz = in_sizes[1];
    const int mf_nnz = in_sizes[4];
    const int rc_nnz = in_sizes[7];
    const int sc_nnz = in_sizes[10];

    int dev = 0;  cudaGetDevice(&dev);
    int sms = 0;  cudaDeviceGetAttribute(&sms, cudaDevAttrMultiProcessorCount, dev);
    unsigned nb = (unsigned)sms;           // 1 CTA per SM: single wave, fast ramp

    hippo_kernel<<<nb, TPB>>>(drive,
                              pp_src, pp_tgt, pp_val, pp_nnz,
                              mf_src, mf_tgt, mf_val, mf_nnz,
                              rc_src, rc_tgt, rc_val, rc_nnz,
                              sc_src, sc_tgt, sc_val, sc_nnz,
                              ec_c, ec_d, dg_c, dg_d, ca3_c, ca3_d, ca1_c, ca1_d,
                              (float*)d_out, nb);
}